// round 3
// baseline (speedup 1.0000x reference)
#include <cuda_runtime.h>
#include <cuda_bf16.h>

// ShiTomasi score, fused single kernel.
// Layout: 8 images of 1080x1920 fp32. Each warp processes a 128-col x 18-row strip;
// each lane owns 4 output columns and a 12-wide register column window.
// Separable Sobel + separable 3x3 box sum, rolling row registers, no smem.

#define IMW 1920
#define IMH 1080
#define RY  18            // output rows per warp strip (multiple of 3)
#define NSX (IMW / 128)   // 15 strips in x
#define NSY (IMH / RY)    // 60 strips in y

__device__ __forceinline__ float4 f4add(float4 a, float4 b) {
    return make_float4(a.x + b.x, a.y + b.y, a.z + b.z, a.w + b.w);
}

// Load 12 columns [c0-4, c0+8) of a (row-clamped) image row, with column clamp
// handled via broadcast at the two image-edge lanes (c0 is a multiple of 4).
__device__ __forceinline__ void load_row(const float* __restrict__ img, int row, int c0,
                                         float (&r)[12]) {
    const float4* p = reinterpret_cast<const float4*>(img + (size_t)row * IMW);
    int q = c0 >> 2;
    float4 B = p[q];
    float4 A = (c0 >= 4)        ? p[q - 1] : make_float4(B.x, B.x, B.x, B.x);
    float4 C = (c0 <= IMW - 8)  ? p[q + 1] : make_float4(B.w, B.w, B.w, B.w);
    r[0] = A.x; r[1] = A.y; r[2]  = A.z; r[3]  = A.w;
    r[4] = B.x; r[5] = B.y; r[6]  = B.z; r[7]  = B.w;
    r[8] = C.x; r[9] = C.y; r[10] = C.z; r[11] = C.w;
}

// Given img rows g-1 (r0), g (r1), g+1 (r2), compute the horizontal 3-sums of
// Ixx/Iyy/Ixy at gradient row g for this lane's 4 output columns.
__device__ __forceinline__ void hrow(const float (&r0)[12], const float (&r1)[12],
                                     const float (&r2)[12], int c0,
                                     float4& hx, float4& hy, float4& hxy) {
    float s[8], v[8];
#pragma unroll
    for (int k = 0; k < 8; k++) {
        s[k] = fmaf(2.f, r1[k + 2], r0[k + 2]) + r2[k + 2]; // vertical [1,2,1]
        v[k] = r2[k + 2] - r0[k + 2];                       // vertical [-1,0,1]
    }
    // positions j=0..5 <-> output-relative columns -1..4
    float pxx[6], pyy[6], pxy[6];
#pragma unroll
    for (int j = 0; j < 6; j++) {
        float ix = s[j + 2] - s[j];
        float iy = fmaf(2.f, v[j + 1], v[j]) + v[j + 2];
        pxx[j] = ix * ix;
        pyy[j] = iy * iy;
        pxy[j] = ix * iy;
    }
    // replicate-pad of the product field at image x-edges:
    if (c0 == 0)       { pxx[0] = pxx[1]; pyy[0] = pyy[1]; pxy[0] = pxy[1]; }
    if (c0 == IMW - 4) { pxx[5] = pxx[4]; pyy[5] = pyy[4]; pxy[5] = pxy[4]; }
    hx  = make_float4(pxx[0] + pxx[1] + pxx[2], pxx[1] + pxx[2] + pxx[3],
                      pxx[2] + pxx[3] + pxx[4], pxx[3] + pxx[4] + pxx[5]);
    hy  = make_float4(pyy[0] + pyy[1] + pyy[2], pyy[1] + pyy[2] + pyy[3],
                      pyy[2] + pyy[3] + pyy[4], pyy[3] + pyy[4] + pyy[5]);
    hxy = make_float4(pxy[0] + pxy[1] + pxy[2], pxy[1] + pxy[2] + pxy[3],
                      pxy[2] + pxy[3] + pxy[4], pxy[3] + pxy[4] + pxy[5]);
}

__device__ __forceinline__ float eig(float a, float b, float c) {
    float ht = (a + b) * 0.5f;
    float dh = (a - b) * 0.5f;
    float d  = sqrtf(fmaf(dh, dh, fmaf(c, c, 1e-10f)));
    return fmaxf(ht - d, 0.f);
}

__device__ __forceinline__ void step(const float* __restrict__ img, float* __restrict__ outb,
                                     int y, int c0,
                                     float (&DST)[12], const float (&RA)[12], const float (&RB)[12],
                                     float4& hpx, float4& hpy, float4& hpxy,   // h(y-1)
                                     float4& hcx, float4& hcy, float4& hcxy,   // h(y)
                                     float4& hnx, float4& hny, float4& hnxy) { // out: h(y+1)
    int gnext = y + 2;
    load_row(img, gnext > IMH - 1 ? IMH - 1 : gnext, c0, DST);
    if (y + 1 < IMH) {
        hrow(RA, RB, DST, c0, hnx, hny, hnxy);
    } else {  // h(clamp(y+1)) = h(H-1) = current row's h
        hnx = hcx; hny = hcy; hnxy = hcxy;
    }
    float4 sxx = f4add(f4add(hpx, hcx), hnx);
    float4 syy = f4add(f4add(hpy, hcy), hny);
    float4 sxy = f4add(f4add(hpxy, hcxy), hnxy);
    float4 o;
    o.x = eig(sxx.x, syy.x, sxy.x);
    o.y = eig(sxx.y, syy.y, sxy.y);
    o.z = eig(sxx.z, syy.z, sxy.z);
    o.w = eig(sxx.w, syy.w, sxy.w);
    *reinterpret_cast<float4*>(outb + (size_t)y * IMW + c0) = o;
}

__global__ __launch_bounds__(256, 2)
void shi_tomasi_kernel(const float* __restrict__ image, float* __restrict__ out, int nwarps) {
    int wid  = blockIdx.x * (blockDim.x >> 5) + (threadIdx.x >> 5);
    if (wid >= nwarps) return;
    int lane = threadIdx.x & 31;

    int sx = wid % NSX;
    int t  = wid / NSX;
    int sy = t % NSY;
    int b  = t / NSY;

    int c0 = sx * 128 + lane * 4;
    int y0 = sy * RY;

    const float* img  = image + (size_t)b * IMH * IMW;
    float*       outb = out   + (size_t)b * IMH * IMW;

    float R0[12], R1[12], R2[12];
    float4 hx0, hy0, hxy0, hx1, hy1, hxy1, hx2, hy2, hxy2;

    // ---- prologue: h(y0-1) and h(y0) ----
    load_row(img, y0 >= 2 ? y0 - 2 : 0, c0, R0);
    load_row(img, y0 >= 1 ? y0 - 1 : 0, c0, R1);
    load_row(img, y0, c0, R2);
    hrow(R0, R1, R2, c0, hx0, hy0, hxy0);        // h(y0-1) (garbage if y0==0, fixed below)
    load_row(img, y0 + 1, c0, R0);               // y0+1 <= IMH-1 always (RY>=2)
    hrow(R1, R2, R0, c0, hx1, hy1, hxy1);        // h(y0)
    if (y0 == 0) { hx0 = hx1; hy0 = hy1; hxy0 = hxy1; }  // h(clamp(-1)) = h(0)

    // rows held: R2 = y0, R0 = y0+1; R1 dead.
#pragma unroll 1
    for (int i = 0; i < RY; i += 3) {
        step(img, outb, y0 + i,     c0, R1, R2, R0,
             hx0, hy0, hxy0, hx1, hy1, hxy1, hx2, hy2, hxy2);
        step(img, outb, y0 + i + 1, c0, R2, R0, R1,
             hx1, hy1, hxy1, hx2, hy2, hxy2, hx0, hy0, hxy0);
        step(img, outb, y0 + i + 2, c0, R0, R1, R2,
             hx2, hy2, hxy2, hx0, hy0, hxy0, hx1, hy1, hxy1);
    }
}

extern "C" void kernel_launch(void* const* d_in, const int* in_sizes, int n_in,
                              void* d_out, int out_size) {
    const float* image = (const float*)d_in[0];
    float* out = (float*)d_out;
    int nimg = in_sizes[0] / (IMH * IMW);          // 8
    int nwarps = nimg * NSX * NSY;                 // 7200
    int warps_per_blk = 8;                         // 256 threads
    int nblocks = (nwarps + warps_per_blk - 1) / warps_per_blk;
    shi_tomasi_kernel<<<nblocks, 256>>>(image, out, nwarps);
}

// round 4
// speedup vs baseline: 1.4502x; 1.4502x over previous
#include <cuda_runtime.h>
#include <cuda_bf16.h>

// ShiTomasi score, fused single kernel.
// Each warp: 128-col x 18-row strip; each lane: 4 output cols, 8-wide register
// column window (cols c0-2 .. c0+5). Separable Sobel + separable 3x3 box,
// rolling row registers, no smem. 3 CTAs/SM resident.

#define IMW 1920
#define IMH 1080
#define RY  18            // output rows per warp strip (multiple of 3)
#define NSX (IMW / 128)   // 15 strips in x
#define NSY (IMH / RY)    // 60 strips in y

__device__ __forceinline__ float4 f4add(float4 a, float4 b) {
    return make_float4(a.x + b.x, a.y + b.y, a.z + b.z, a.w + b.w);
}

// Load the 8 columns [c0-2, c0+6) of a (row-clamped) image row. Column clamp
// handled via broadcast at the two image-edge lanes (c0 is a multiple of 4).
__device__ __forceinline__ void load_row(const float* __restrict__ img, int row, int c0,
                                         float (&r)[8]) {
    const float4* p = reinterpret_cast<const float4*>(img + (size_t)row * IMW);
    int q = c0 >> 2;
    float4 B = p[q];
    float4 A = (c0 >= 4)        ? p[q - 1] : make_float4(B.x, B.x, B.x, B.x);
    float4 C = (c0 <= IMW - 8)  ? p[q + 1] : make_float4(B.w, B.w, B.w, B.w);
    r[0] = A.z; r[1] = A.w;
    r[2] = B.x; r[3] = B.y; r[4] = B.z; r[5] = B.w;
    r[6] = C.x; r[7] = C.y;
}

// Given img rows g-1 (r0), g (r1), g+1 (r2) (8-wide windows, cols c0-2..c0+5),
// compute horizontal 3-sums of Ixx/Iyy/Ixy at gradient row g for 4 output cols.
__device__ __forceinline__ void hrow(const float (&r0)[8], const float (&r1)[8],
                                     const float (&r2)[8], int c0,
                                     float4& hx, float4& hy, float4& hxy) {
    float s[8], v[8];
#pragma unroll
    for (int k = 0; k < 8; k++) {
        s[k] = fmaf(2.f, r1[k], r0[k]) + r2[k]; // vertical [1,2,1]
        v[k] = r2[k] - r0[k];                   // vertical [-1,0,1]
    }
    // positions j=0..5 <-> output-relative columns -1..4
    float pxx[6], pyy[6], pxy[6];
#pragma unroll
    for (int j = 0; j < 6; j++) {
        float ix = s[j + 2] - s[j];
        float iy = fmaf(2.f, v[j + 1], v[j]) + v[j + 2];
        pxx[j] = ix * ix;
        pyy[j] = iy * iy;
        pxy[j] = ix * iy;
    }
    // replicate-pad of the product field at image x-edges:
    if (c0 == 0)       { pxx[0] = pxx[1]; pyy[0] = pyy[1]; pxy[0] = pxy[1]; }
    if (c0 == IMW - 4) { pxx[5] = pxx[4]; pyy[5] = pyy[4]; pxy[5] = pxy[4]; }
    hx  = make_float4(pxx[0] + pxx[1] + pxx[2], pxx[1] + pxx[2] + pxx[3],
                      pxx[2] + pxx[3] + pxx[4], pxx[3] + pxx[4] + pxx[5]);
    hy  = make_float4(pyy[0] + pyy[1] + pyy[2], pyy[1] + pyy[2] + pyy[3],
                      pyy[2] + pyy[3] + pyy[4], pyy[3] + pyy[4] + pyy[5]);
    hxy = make_float4(pxy[0] + pxy[1] + pxy[2], pxy[1] + pxy[2] + pxy[3],
                      pxy[2] + pxy[3] + pxy[4], pxy[3] + pxy[4] + pxy[5]);
}

__device__ __forceinline__ float eig(float a, float b, float c) {
    float ht = (a + b) * 0.5f;
    float dh = (a - b) * 0.5f;
    float x  = fmaf(dh, dh, fmaf(c, c, 1e-10f));
    float d  = x * rsqrtf(x);            // sqrt(x), x >= 1e-10 so well-defined
    return fmaxf(ht - d, 0.f);
}

__device__ __forceinline__ void step(const float* __restrict__ img, float* __restrict__ outb,
                                     int y, int c0,
                                     float (&DST)[8], const float (&RA)[8], const float (&RB)[8],
                                     float4& hpx, float4& hpy, float4& hpxy,   // h(y-1)
                                     float4& hcx, float4& hcy, float4& hcxy,   // h(y)
                                     float4& hnx, float4& hny, float4& hnxy) { // out: h(y+1)
    int gnext = y + 2;
    load_row(img, gnext > IMH - 1 ? IMH - 1 : gnext, c0, DST);
    if (y + 1 < IMH) {
        hrow(RA, RB, DST, c0, hnx, hny, hnxy);
    } else {  // h(clamp(y+1)) = h(H-1) = current row's h
        hnx = hcx; hny = hcy; hnxy = hcxy;
    }
    float4 sxx = f4add(f4add(hpx, hcx), hnx);
    float4 syy = f4add(f4add(hpy, hcy), hny);
    float4 sxy = f4add(f4add(hpxy, hcxy), hnxy);
    float4 o;
    o.x = eig(sxx.x, syy.x, sxy.x);
    o.y = eig(sxx.y, syy.y, sxy.y);
    o.z = eig(sxx.z, syy.z, sxy.z);
    o.w = eig(sxx.w, syy.w, sxy.w);
    *reinterpret_cast<float4*>(outb + (size_t)y * IMW + c0) = o;
}

__global__ __launch_bounds__(256, 3)
void shi_tomasi_kernel(const float* __restrict__ image, float* __restrict__ out, int nwarps) {
    int wid  = blockIdx.x * (blockDim.x >> 5) + (threadIdx.x >> 5);
    if (wid >= nwarps) return;
    int lane = threadIdx.x & 31;

    int sx = wid % NSX;
    int t  = wid / NSX;
    int sy = t % NSY;
    int b  = t / NSY;

    int c0 = sx * 128 + lane * 4;
    int y0 = sy * RY;

    const float* img  = image + (size_t)b * IMH * IMW;
    float*       outb = out   + (size_t)b * IMH * IMW;

    float R0[8], R1[8], R2[8];
    float4 hx0, hy0, hxy0, hx1, hy1, hxy1, hx2, hy2, hxy2;

    // ---- prologue: h(y0-1) and h(y0) ----
    load_row(img, y0 >= 2 ? y0 - 2 : 0, c0, R0);
    load_row(img, y0 >= 1 ? y0 - 1 : 0, c0, R1);
    load_row(img, y0, c0, R2);
    hrow(R0, R1, R2, c0, hx0, hy0, hxy0);        // h(y0-1) (garbage if y0==0, fixed below)
    load_row(img, y0 + 1, c0, R0);               // y0+1 <= IMH-1 always (RY>=2)
    hrow(R1, R2, R0, c0, hx1, hy1, hxy1);        // h(y0)
    if (y0 == 0) { hx0 = hx1; hy0 = hy1; hxy0 = hxy1; }  // h(clamp(-1)) = h(0)

    // rows held: R2 = y0, R0 = y0+1; R1 dead.
#pragma unroll 1
    for (int i = 0; i < RY; i += 3) {
        step(img, outb, y0 + i,     c0, R1, R2, R0,
             hx0, hy0, hxy0, hx1, hy1, hxy1, hx2, hy2, hxy2);
        step(img, outb, y0 + i + 1, c0, R2, R0, R1,
             hx1, hy1, hxy1, hx2, hy2, hxy2, hx0, hy0, hxy0);
        step(img, outb, y0 + i + 2, c0, R0, R1, R2,
             hx2, hy2, hxy2, hx0, hy0, hxy0, hx1, hy1, hxy1);
    }
}

extern "C" void kernel_launch(void* const* d_in, const int* in_sizes, int n_in,
                              void* d_out, int out_size) {
    const float* image = (const float*)d_in[0];
    float* out = (float*)d_out;
    int nimg = in_sizes[0] / (IMH * IMW);          // 8
    int nwarps = nimg * NSX * NSY;                 // 7200
    int warps_per_blk = 8;                         // 256 threads
    int nblocks = (nwarps + warps_per_blk - 1) / warps_per_blk;
    shi_tomasi_kernel<<<nblocks, 256>>>(image, out, nwarps);
}